// round 14
// baseline (speedup 1.0000x reference)
#include <cuda_runtime.h>
#include <cuda_bf16.h>
#include <cstdint>

// Problem constants (fixed by the reference)
#define BB 32
#define LL 4096
#define HH 1024
#define GCH 64           // g-dimension chunks for the hid@W gemv (16 g each)
#define GPC (HH / GCH)   // 16 g per chunk
#define BCH 8            // b per thread in gemv (4 b-groups)
#define LPW 32           // encoder rows handled per warp in energies (2 halves of 16)
#define WPB 8            // warps per block in energies
#define XCTAS (LL / (WPB * LPW))   // 16 x-CTAs per b

// Scratch (allocation-free rule: __device__ globals)
__device__ float g_vpart[GCH * BB * HH];   // 8 MiB
__device__ float g_v[BB * HH];             // 128 KB
__device__ float g_energy[BB * LL];        // 512 KB
__device__ int   g_cnt[BB];                // arrival counters (zeroed by fold kernel)

// ---------------------------------------------------------------------------
// Kernel 1: partial v[b,h] over a 16-wide g chunk, 8-wide b group, 4 h/thread.
// grid (HH/512, GCH, BB/BCH) = (2,64,4) = 512 CTAs, 128 threads.
// W as 16 LDG.128 (deep MLP), hid transposed in smem so each g needs 2
// LDS.128; 512 FMA/thread -> ~10:1 FMA:aux ratio.
// ---------------------------------------------------------------------------
__global__ void gemv_partial_kernel(const float* __restrict__ hid,
                                    const float* __restrict__ W) {
    const int t  = threadIdx.x;
    const int h4 = blockIdx.x * 512 + t * 4;   // 4 consecutive h per thread
    const int g0 = blockIdx.y * GPC;           // 16-wide g chunk
    const int b0 = blockIdx.z * BCH;           // 8-wide b group

    // Stage hid[b0:b0+8][g0:g0+16] transposed: hsh_t[g][b], 128 floats.
    __shared__ float hsh_t[GPC][BCH];
    if (t < 32) {
        const int b  = t >> 2;
        const int gg = (t & 3) * 4;
        const float4 hv = *reinterpret_cast<const float4*>(
            hid + (size_t)(b0 + b) * HH + g0 + gg);
        hsh_t[gg + 0][b] = hv.x; hsh_t[gg + 1][b] = hv.y;
        hsh_t[gg + 2][b] = hv.z; hsh_t[gg + 3][b] = hv.w;
    }
    __syncthreads();

    float4 acc[BCH];
#pragma unroll
    for (int b = 0; b < BCH; ++b) acc[b] = make_float4(0.f, 0.f, 0.f, 0.f);

    const float4* Wv = reinterpret_cast<const float4*>(W) + (size_t)g0 * (HH / 4) + (h4 >> 2);
#pragma unroll
    for (int g = 0; g < GPC; ++g) {
        const float4 w = Wv[(size_t)g * (HH / 4)];          // LDG.128, coalesced
        const float4 hlo = *reinterpret_cast<const float4*>(&hsh_t[g][0]);  // LDS.128
        const float4 hhi = *reinterpret_cast<const float4*>(&hsh_t[g][4]);  // LDS.128
        const float hb[8] = {hlo.x, hlo.y, hlo.z, hlo.w, hhi.x, hhi.y, hhi.z, hhi.w};
#pragma unroll
        for (int b = 0; b < BCH; ++b) {
            acc[b].x = fmaf(hb[b], w.x, acc[b].x);
            acc[b].y = fmaf(hb[b], w.y, acc[b].y);
            acc[b].z = fmaf(hb[b], w.z, acc[b].z);
            acc[b].w = fmaf(hb[b], w.w, acc[b].w);
        }
    }

    float* vp = g_vpart + (size_t)blockIdx.y * BB * HH;
#pragma unroll
    for (int b = 0; b < BCH; ++b)
        *reinterpret_cast<float4*>(vp + (size_t)(b0 + b) * HH + h4) = acc[b];  // STG.128
}

// ---------------------------------------------------------------------------
// Kernel 2: fold the GCH partials into g_v (float4, deep MLP); also re-zero
// the arrival counters for the fused softmax.
// ---------------------------------------------------------------------------
__global__ void fold_v_kernel() {
    const int i = blockIdx.x * 128 + threadIdx.x;   // float4 index, i < BB*HH/4
    if (blockIdx.x == 0 && threadIdx.x < BB) g_cnt[threadIdx.x] = 0;
    const float4* vp4 = reinterpret_cast<const float4*>(g_vpart);
    float4 s = make_float4(0.f, 0.f, 0.f, 0.f);
#pragma unroll 16
    for (int c = 0; c < GCH; ++c) {
        const float4 x = vp4[(size_t)c * (BB * HH / 4) + i];
        s.x += x.x; s.y += x.y; s.z += x.z; s.w += x.w;
    }
    reinterpret_cast<float4*>(g_v)[i] = s;
}

// ---------------------------------------------------------------------------
// Kernel 3: energies[b,l] = enc[l,b,:] . v[b,:]  + fused row softmax epilogue.
// grid (16, 32) = 512 CTAs -> ONE wave at 4 CTAs/SM. Each warp: 32 rows as 2
// deferred-reduction batches of 16. v[b] in 4 KB smem. Last-arriving CTA per
// b (fence + atomic counter) does the 4096-wide softmax.
// ---------------------------------------------------------------------------
__global__ void __launch_bounds__(32 * WPB, 4)
energies_kernel(const float* __restrict__ enc, float* __restrict__ out) {
    const int warp = threadIdx.x >> 5;
    const int lane = threadIdx.x & 31;
    const int b    = blockIdx.y;
    const int l0   = (blockIdx.x * WPB + warp) * LPW;

    __shared__ float4 vsh[HH / 4];   // 4 KB: v[b] as 256 float4
    vsh[threadIdx.x] = reinterpret_cast<const float4*>(g_v + (size_t)b * HH)[threadIdx.x];
    __syncthreads();

    const float4* ep = reinterpret_cast<const float4*>(enc) +
                       ((size_t)l0 * BB + b) * (HH / 4);
    const size_t row_stride = (size_t)BB * (HH / 4);

#pragma unroll
    for (int half = 0; half < 2; ++half) {
        float acc[16];
#pragma unroll
        for (int j = 0; j < 16; ++j) acc[j] = 0.f;

        for (int j = 0; j < 16; ++j) {
            const float4* row = ep + (size_t)(half * 16 + j) * row_stride;
            float4 x[8];
#pragma unroll
            for (int i = 0; i < 8; ++i)
                x[i] = __ldcs(row + i * 32 + lane);    // 8 LDG.128 in flight
            float a0 = 0.f, a1 = 0.f, a2 = 0.f, a3 = 0.f;
#pragma unroll
            for (int i = 0; i < 8; ++i) {
                const float4 vv = vsh[i * 32 + lane];  // conflict-free LDS.128
                a0 = fmaf(x[i].x, vv.x, a0);
                a1 = fmaf(x[i].y, vv.y, a1);
                a2 = fmaf(x[i].z, vv.z, a2);
                a3 = fmaf(x[i].w, vv.w, a3);
            }
            acc[j] = (a0 + a1) + (a2 + a3);
        }

        // Deferred butterfly reductions: 16 independent chains overlap.
#pragma unroll
        for (int j = 0; j < 16; ++j) {
#pragma unroll
            for (int o = 16; o; o >>= 1)
                acc[j] += __shfl_xor_sync(0xffffffffu, acc[j], o);
        }
        if (lane == 0) {
            float4* eo = reinterpret_cast<float4*>(g_energy + (size_t)b * LL + l0 + half * 16);
#pragma unroll
            for (int q = 0; q < 4; ++q)
                eo[q] = make_float4(acc[4 * q], acc[4 * q + 1], acc[4 * q + 2], acc[4 * q + 3]);
        }
    }

    // ---- arrival: is this the last CTA for row b? ----
    __threadfence();
    __syncthreads();
    __shared__ int s_last;
    if (threadIdx.x == 0)
        s_last = (atomicAdd(&g_cnt[b], 1) == XCTAS - 1);
    __syncthreads();
    if (!s_last) return;

    // ---- fused softmax over L=4096 for row b (256 threads, 16 vals each) ----
    const int t = threadIdx.x;
    __shared__ float sh[WPB];
    __shared__ float bcast;
    const float4* ebase = reinterpret_cast<const float4*>(g_energy + (size_t)b * LL);

    float4 e[4];
    float m = -1e30f;
#pragma unroll
    for (int k = 0; k < 4; ++k) {
        e[k] = ebase[t + k * 256];
        m = fmaxf(m, fmaxf(fmaxf(e[k].x, e[k].y), fmaxf(e[k].z, e[k].w)));
    }
#pragma unroll
    for (int o = 16; o; o >>= 1)
        m = fmaxf(m, __shfl_xor_sync(0xffffffffu, m, o));
    if (lane == 0) sh[warp] = m;
    __syncthreads();
    if (t < 32) {
        float v = sh[t & (WPB - 1)];
#pragma unroll
        for (int o = WPB / 2; o; o >>= 1)
            v = fmaxf(v, __shfl_xor_sync(0xffffffffu, v, o));
        if (t == 0) bcast = v;
    }
    __syncthreads();
    m = bcast;

    float s = 0.f;
#pragma unroll
    for (int k = 0; k < 4; ++k) {
        e[k].x = __expf(e[k].x - m); e[k].y = __expf(e[k].y - m);
        e[k].z = __expf(e[k].z - m); e[k].w = __expf(e[k].w - m);
        s += (e[k].x + e[k].y) + (e[k].z + e[k].w);
    }
#pragma unroll
    for (int o = 16; o; o >>= 1)
        s += __shfl_xor_sync(0xffffffffu, s, o);
    if (lane == 0) sh[warp] = s;
    __syncthreads();
    if (t < 32) {
        float v = sh[t & (WPB - 1)];
#pragma unroll
        for (int o = WPB / 2; o; o >>= 1)
            v += __shfl_xor_sync(0xffffffffu, v, o);
        if (t == 0) bcast = v;
    }
    __syncthreads();
    const float inv = 1.0f / bcast;

    float4* op = reinterpret_cast<float4*>(out + (size_t)b * LL);
#pragma unroll
    for (int k = 0; k < 4; ++k) {
        e[k].x *= inv; e[k].y *= inv; e[k].z *= inv; e[k].w *= inv;
        op[t + k * 256] = e[k];
    }
}

// ---------------------------------------------------------------------------
extern "C" void kernel_launch(void* const* d_in, const int* in_sizes, int n_in,
                              void* d_out, int out_size) {
    // Identify inputs by element count (all distinct): robust to ordering.
    const float* hid = nullptr;   // 32*1024      = 32768
    const float* enc = nullptr;   // 4096*32*1024 = 134217728
    const float* W   = nullptr;   // 1024*1024    = 1048576
    for (int i = 0; i < n_in; ++i) {
        const int s = in_sizes[i];
        if (s == BB * HH)            hid = (const float*)d_in[i];
        else if (s == HH * HH)       W   = (const float*)d_in[i];
        else if (s == 1024)          { /* bias: softmax-invariant (and zero) */ }
        else                         enc = (const float*)d_in[i];
    }
    float* out = (float*)d_out;

    gemv_partial_kernel<<<dim3(HH / 512, GCH, BB / BCH), 128>>>(hid, W);
    fold_v_kernel<<<(BB * HH / 4) / 128, 128>>>();
    energies_kernel<<<dim3(XCTAS, BB), 32 * WPB>>>(enc, out);
}